// round 12
// baseline (speedup 1.0000x reference)
#include <cuda_runtime.h>
#include <math.h>

#define CC   16
#define DIMN 16
#define LL   6

typedef unsigned long long u64;

// ---------------- f32x2 packed helpers (sm_103a) -------------------
__device__ __forceinline__ u64 pk2(float lo, float hi) {
    u64 r; asm("mov.b64 %0, {%1, %2};" : "=l"(r) : "f"(lo), "f"(hi)); return r;
}
__device__ __forceinline__ void up2(float& lo, float& hi, u64 v) {
    asm("mov.b64 {%0, %1}, %2;" : "=f"(lo), "=f"(hi) : "l"(v));
}
__device__ __forceinline__ u64 ffma2(u64 a, u64 b, u64 c) {
    u64 d; asm("fma.rn.f32x2 %0, %1, %2, %3;" : "=l"(d) : "l"(a), "l"(b), "l"(c)); return d;
}
__device__ __forceinline__ u64 add2(u64 a, u64 b) {
    u64 d; asm("add.rn.f32x2 %0, %1, %2;" : "=l"(d) : "l"(a), "l"(b)); return d;
}
__device__ __forceinline__ u64 mul2(u64 a, u64 b) {
    u64 d; asm("mul.rn.f32x2 %0, %1, %2;" : "=l"(d) : "l"(a), "l"(b)); return d;
}
__device__ __forceinline__ float fast_sqrt(float x) {
    float r; asm("sqrt.approx.f32 %0, %1;" : "=f"(r) : "f"(x)); return r;
}
__device__ __forceinline__ float fast_rcp(float x) {
    float r; asm("rcp.approx.f32 %0, %1;" : "=f"(r) : "f"(x)); return r;
}

// per-layer scalar tail: (e0+e1) -> r -> h -> f1,f2; updates P1,P2; returns f1 pair
__device__ __forceinline__ u64 tail_step(u64 e0, u64 e1, ulonglong2 pab, u64 abp,
                                         u64& P1p, u64& P2p) {
    const u64 ONE2 = pk2(1.0f, 1.0f);
    u64 r2p = add2(e0, e1);
    float rA, rB; up2(rA, rB, r2p);
    u64 rp = pk2(fast_sqrt(rA), fast_sqrt(rB));
    u64 up = add2(pab.x, rp);                 // alpha + r
    float uA, uB; up2(uA, uB, up);
    u64 hp = pk2(fast_rcp(uA), fast_rcp(uB));
    u64 f1p = ffma2(pab.y, hp, ONE2);         // 1 + beta*h
    u64 f2p = ffma2(abp, mul2(hp, hp), ONE2); // 1 + alpha*beta*h^2
    P1p = mul2(P1p, f1p);
    P2p = mul2(P2p, f2p);
    return f1p;
}

// ---------------- fused density kernel: per-block setup prologue + R10 mainloop ----------------
__global__ void __launch_bounds__(128, 5)
density_kernel(const float* __restrict__ z, const float* __restrict__ z0,
               const float* __restrict__ la, const float* __restrict__ be,
               const float* __restrict__ mean, const float* __restrict__ cov,
               float* __restrict__ out, int N)
{
    // Deltas, cp-INNERMOST layout: entry (l, j, cp) holds dims {2j,2j+1} for c0=2cp, c1=2cp+1
    __shared__ ulonglong2 s_negD[LL * 8 * 8];     // 6 KB, index l*64 + j*8 + cp
    __shared__ ulonglong2 s_m5[8 * 8];            // 1 KB, index j*8 + cp
    __shared__ ulonglong2 s_parab[LL * 8];        // {(a,a'),(b,b')}
    __shared__ u64        s_parc[LL * 8];         // (a*b) pair
    __shared__ u64        s_hld2[8];              // half_logdet pair
    __shared__ float      s_hldf[CC];
    __shared__ float      s_Linv[CC * DIMN * DIMN]; // 16 KB (cold path only)
    __shared__ int        s_bad;

    int t = threadIdx.x;
    if (t == 0) s_bad = 0;
    __syncthreads();

    // ---- per-block setup: params from raw inputs (all L2-broadcast reads) ----
    // packed params per (layer, c-pair): 48 entries
    if (t < LL * 8) {
        int l = t / 8, cp = t % 8;
        int c0 = 2 * cp, c1 = c0 + 1;
        float a0 = __expf(la[l * CC + c0]) , a1 = __expf(la[l * CC + c1]);
        // use accurate expf to match reference closely
        a0 = expf(la[l * CC + c0]); a1 = expf(la[l * CC + c1]);
        float b0 = be[l * CC + c0], b1 = be[l * CC + c1];
        ulonglong2 v; v.x = pk2(a0, a1); v.y = pk2(b0, b1);
        s_parab[t] = v;
        s_parc[t]  = pk2(a0 * b0, a1 * b1);
    }
    // layer deltas: 384 entries, 3 per thread
    for (int i = t; i < LL * 8 * 8; i += 128) {
        int l = i / 64, rem = i % 64, j = rem / 8, cp = rem % 8;
        int c0 = 2 * cp, c1 = c0 + 1;
        int b0 = (l * CC + c0) * DIMN + 2 * j;
        int b1 = (l * CC + c1) * DIMN + 2 * j;
        float x0 = -z0[b0], y0 = -z0[b0 + 1];
        float x1 = -z0[b1], y1 = -z0[b1 + 1];
        if (l > 0) {
            int p0 = ((l - 1) * CC + c0) * DIMN + 2 * j;
            int p1 = ((l - 1) * CC + c1) * DIMN + 2 * j;
            x0 += z0[p0]; y0 += z0[p0 + 1];
            x1 += z0[p1]; y1 += z0[p1 + 1];
        }
        ulonglong2 v; v.x = pk2(x0, x1); v.y = pk2(y0, y1);
        s_negD[i] = v;
    }
    // final offset z0_5 - mean: 64 entries
    if (t < 64) {
        int j = t / 8, cp = t % 8;
        int c0 = 2 * cp, c1 = c0 + 1;
        int b0 = (5 * CC + c0) * DIMN + 2 * j;
        int b1 = (5 * CC + c1) * DIMN + 2 * j;
        int m0 = c0 * DIMN + 2 * j, m1 = c1 * DIMN + 2 * j;
        ulonglong2 v;
        v.x = pk2(z0[b0]     - mean[m0],     z0[b1]     - mean[m1]);
        v.y = pk2(z0[b0 + 1] - mean[m0 + 1], z0[b1 + 1] - mean[m1 + 1]);
        s_m5[t] = v;
    }
    // identity check on cov (16 KB, L2-resident across blocks)
    {
        int bad = 0;
        for (int i = t; i < CC * DIMN * DIMN; i += 128) {
            float e = (((i % (DIMN * DIMN)) % (DIMN + 1)) == 0) ? 1.0f : 0.0f;
            if (cov[i] != e) bad = 1;
        }
        if (bad) atomicOr(&s_bad, 1);
    }
    __syncthreads();
    int ident = (s_bad == 0);

    if (ident) {
        if (t < 8) s_hld2[t] = 0ull;   // pk2(0,0)
    } else {
        // cold path: per-block Cholesky + triangular inverse for all 16 components
        if (t < CC) {
            int c = t;
            float Lm[DIMN][DIMN];
            const float* A = cov + c * DIMN * DIMN;
            #pragma unroll 1
            for (int j = 0; j < DIMN; j++) {
                float s = A[j * DIMN + j];
                #pragma unroll 1
                for (int k = 0; k < j; k++) s -= Lm[j][k] * Lm[j][k];
                float d = sqrtf(s);
                Lm[j][j] = d;
                float inv = 1.0f / d;
                #pragma unroll 1
                for (int i = j + 1; i < DIMN; i++) {
                    float s2 = A[i * DIMN + j];
                    #pragma unroll 1
                    for (int k = 0; k < j; k++) s2 -= Lm[i][k] * Lm[j][k];
                    Lm[i][j] = s2 * inv;
                }
            }
            float hld = 0.0f;
            #pragma unroll 1
            for (int j = 0; j < DIMN; j++) hld += logf(Lm[j][j]);
            s_hldf[c] = hld;

            float Li[DIMN][DIMN];
            #pragma unroll 1
            for (int j = 0; j < DIMN; j++) {
                for (int i = 0; i < DIMN; i++) Li[i][j] = 0.0f;
                Li[j][j] = 1.0f / Lm[j][j];
                #pragma unroll 1
                for (int i = j + 1; i < DIMN; i++) {
                    float s3 = 0.0f;
                    #pragma unroll 1
                    for (int k = j; k < i; k++) s3 += Lm[i][k] * Li[k][j];
                    Li[i][j] = -s3 / Lm[i][i];
                }
            }
            for (int i = 0; i < DIMN; i++)
                for (int j = 0; j < DIMN; j++)
                    s_Linv[(c * DIMN + i) * DIMN + j] = Li[i][j];
        }
        __syncthreads();
        if (t < 8) s_hld2[t] = pk2(s_hldf[2 * t], s_hldf[2 * t + 1]);
    }
    __syncthreads();

    int n = blockIdx.x * 128 + t;
    if (n >= N) return;

    // ---- mainloop: identical to R10 (best known) ----
    const float4* zr = (const float4*)(z + (size_t)n * DIMN);
    float4 q0 = zr[0], q1 = zr[1], q2 = zr[2], q3 = zr[3];
    float zf[16] = { q0.x, q0.y, q0.z, q0.w, q1.x, q1.y, q1.z, q1.w,
                     q2.x, q2.y, q2.z, q2.w, q3.x, q3.y, q3.z, q3.w };

    const float HALF_DIM_LOG2PI = 14.7030165f;   // 0.5 * 16 * log(2*pi)
    const u64 ONE2 = pk2(1.0f, 1.0f);

    #pragma unroll 1
    for (int cp = 0; cp < 8; cp++) {
        const ulonglong2* dp = &s_negD[cp];

        u64 s[16];
        u64 e0 = 0ull, e1 = 0ull;

        // ---- layer 0: s = z - z0_0 ----
        #pragma unroll
        for (int j = 0; j < 8; j++) {
            ulonglong2 dd = dp[j * 8];
            u64 za = pk2(zf[2 * j],     zf[2 * j]);
            u64 zb = pk2(zf[2 * j + 1], zf[2 * j + 1]);
            s[2 * j]     = add2(za, dd.x);
            s[2 * j + 1] = add2(zb, dd.y);
            e0 = ffma2(s[2 * j],     s[2 * j],     e0);
            e1 = ffma2(s[2 * j + 1], s[2 * j + 1], e1);
        }

        u64 P1p = ONE2, P2p = ONE2, f1p;

        // ---- layers 1..5: prefetch layer-l deltas, tail(l-1) over them, update ----
        #pragma unroll
        for (int l = 1; l < LL; l++) {
            const ulonglong2* dl = dp + l * 64;
            ulonglong2 p0 = dl[0], p1 = dl[8], p2 = dl[16], p3 = dl[24];
            ulonglong2 pab = s_parab[(l - 1) * 8 + cp];
            u64 abp = s_parc[(l - 1) * 8 + cp];

            f1p = tail_step(e0, e1, pab, abp, P1p, P2p);

            e0 = 0ull; e1 = 0ull;
            s[0] = ffma2(f1p, s[0], p0.x); s[1] = ffma2(f1p, s[1], p0.y);
            e0 = ffma2(s[0], s[0], e0);    e1 = ffma2(s[1], s[1], e1);
            s[2] = ffma2(f1p, s[2], p1.x); s[3] = ffma2(f1p, s[3], p1.y);
            e0 = ffma2(s[2], s[2], e0);    e1 = ffma2(s[3], s[3], e1);
            s[4] = ffma2(f1p, s[4], p2.x); s[5] = ffma2(f1p, s[5], p2.y);
            e0 = ffma2(s[4], s[4], e0);    e1 = ffma2(s[5], s[5], e1);
            s[6] = ffma2(f1p, s[6], p3.x); s[7] = ffma2(f1p, s[7], p3.y);
            e0 = ffma2(s[6], s[6], e0);    e1 = ffma2(s[7], s[7], e1);
            #pragma unroll
            for (int j = 4; j < 8; j++) {
                ulonglong2 dd = dl[j * 8];
                s[2 * j]     = ffma2(f1p, s[2 * j],     dd.x);
                s[2 * j + 1] = ffma2(f1p, s[2 * j + 1], dd.y);
                e0 = ffma2(s[2 * j],     s[2 * j],     e0);
                e1 = ffma2(s[2 * j + 1], s[2 * j + 1], e1);
            }
        }

        // ---- final: prefetch m5, tail(5), then q = |f1*s + m5|^2 ----
        const ulonglong2* mp = &s_m5[cp];
        ulonglong2 m0 = mp[0], m1 = mp[8], m2 = mp[16], m3 = mp[24];
        ulonglong2 pab5 = s_parab[5 * 8 + cp];
        u64 abp5 = s_parc[5 * 8 + cp];

        f1p = tail_step(e0, e1, pab5, abp5, P1p, P2p);

        float qA, qB;
        if (ident) {
            u64 a0 = 0ull, a1 = 0ull;
            u64 dx, dy;
            dx = ffma2(f1p, s[0], m0.x); dy = ffma2(f1p, s[1], m0.y);
            a0 = ffma2(dx, dx, a0);      a1 = ffma2(dy, dy, a1);
            dx = ffma2(f1p, s[2], m1.x); dy = ffma2(f1p, s[3], m1.y);
            a0 = ffma2(dx, dx, a0);      a1 = ffma2(dy, dy, a1);
            dx = ffma2(f1p, s[4], m2.x); dy = ffma2(f1p, s[5], m2.y);
            a0 = ffma2(dx, dx, a0);      a1 = ffma2(dy, dy, a1);
            dx = ffma2(f1p, s[6], m3.x); dy = ffma2(f1p, s[7], m3.y);
            a0 = ffma2(dx, dx, a0);      a1 = ffma2(dy, dy, a1);
            #pragma unroll
            for (int j = 4; j < 8; j++) {
                ulonglong2 mm = mp[j * 8];
                dx = ffma2(f1p, s[2 * j],     mm.x);
                dy = ffma2(f1p, s[2 * j + 1], mm.y);
                a0 = ffma2(dx, dx, a0);
                a1 = ffma2(dy, dy, a1);
            }
            u64 qp = add2(a0, a1);
            up2(qA, qB, qp);
        } else {
            // cold path: triangular solve with Linv from shared
            float drA[DIMN], drB[DIMN];
            #pragma unroll
            for (int j = 0; j < 8; j++) {
                ulonglong2 mm = mp[j * 8];
                u64 dx = ffma2(f1p, s[2 * j],     mm.x);
                u64 dy = ffma2(f1p, s[2 * j + 1], mm.y);
                up2(drA[2 * j],     drB[2 * j],     dx);
                up2(drA[2 * j + 1], drB[2 * j + 1], dy);
            }
            qA = 0.0f; qB = 0.0f;
            const float* LpA = &s_Linv[2 * cp * DIMN * DIMN];
            const float* LpB = LpA + DIMN * DIMN;
            #pragma unroll 1
            for (int j = 0; j < DIMN; j++) {
                float sa = 0.0f, sb = 0.0f;
                #pragma unroll 1
                for (int i = 0; i <= j; i++) {
                    sa = fmaf(LpA[j * DIMN + i], drA[i], sa);
                    sb = fmaf(LpB[j * DIMN + i], drB[i], sb);
                }
                qA = fmaf(sa, sa, qA);
                qB = fmaf(sb, sb, qB);
            }
        }

        // log_det_jac total = log(P1^15 * P2), packed pow15
        u64 p2  = mul2(P1p, P1p);
        u64 p4  = mul2(p2, p2);
        u64 p8  = mul2(p4, p4);
        u64 g   = mul2(mul2(mul2(p8, p4), mul2(p2, P1p)), P2p);
        float gA, gB; up2(gA, gB, g);
        float hldA, hldB; up2(hldA, hldB, s_hld2[cp]);
        float vA = fmaf(-0.5f, qA, -HALF_DIM_LOG2PI) - hldA + __logf(gA);
        float vB = fmaf(-0.5f, qB, -HALF_DIM_LOG2PI) - hldB + __logf(gB);
        if (vA != vA) vA = __int_as_float(0xff800000);  // NaN -> -inf
        if (vB != vB) vB = __int_as_float(0xff800000);

        *(float2*)(out + (size_t)n * CC + 2 * cp) = make_float2(vA, vB);
    }
}

// ---------------- launch: single fused kernel ----------------
extern "C" void kernel_launch(void* const* d_in, const int* in_sizes, int n_in,
                              void* d_out, int out_size) {
    const float* z    = (const float*)d_in[0];
    const float* z0   = (const float*)d_in[1];
    const float* la   = (const float*)d_in[2];
    const float* be   = (const float*)d_in[3];
    const float* mean = (const float*)d_in[4];
    const float* cov  = (const float*)d_in[5];
    float* out = (float*)d_out;

    int N = in_sizes[0] / DIMN;

    int blocks = (N + 127) / 128;
    density_kernel<<<blocks, 128>>>(z, z0, la, be, mean, cov, out, N);
}

// round 13
// speedup vs baseline: 1.6463x; 1.6463x over previous
#include <cuda_runtime.h>
#include <math.h>

#define CC   16
#define DIMN 16
#define LL   6

typedef unsigned long long u64;

// ---------------- device-global precomputed params ----------------
// Deltas, cp-INNERMOST layout: entry (l, j, cp) holds dims {2j,2j+1} for c0=2cp, c1=2cp+1:
//   .x = ( -D_l[c0][2j],   -D_l[c1][2j]   )
//   .y = ( -D_l[c0][2j+1], -D_l[c1][2j+1] )   where -D_0 = -z0_0, -D_l = z0_{l-1}-z0_l
__device__ ulonglong2 g_negD2[LL * 8 * 8];   // index l*64 + j*8 + cp
__device__ ulonglong2 g_m52[8 * 8];          // (z0_5 - mean), index j*8 + cp
__device__ ulonglong2 g_parab[LL * 8];       // {(a_c0,a_c1), (b_c0,b_c1)}, index l*8+cp
__device__ u64        g_parc[LL * 8];        // (a*b) pair
__device__ u64        g_hld2[8];             // half_logdet pair
__device__ float      g_hld[CC];
__device__ float      g_Linv[CC * DIMN * DIMN];
__device__ int        g_ident;

// ---------------- f32x2 packed helpers (sm_103a) -------------------
__device__ __forceinline__ u64 pk2(float lo, float hi) {
    u64 r; asm("mov.b64 %0, {%1, %2};" : "=l"(r) : "f"(lo), "f"(hi)); return r;
}
__device__ __forceinline__ void up2(float& lo, float& hi, u64 v) {
    asm("mov.b64 {%0, %1}, %2;" : "=f"(lo), "=f"(hi) : "l"(v));
}
__device__ __forceinline__ u64 ffma2(u64 a, u64 b, u64 c) {
    u64 d; asm("fma.rn.f32x2 %0, %1, %2, %3;" : "=l"(d) : "l"(a), "l"(b), "l"(c)); return d;
}
__device__ __forceinline__ u64 add2(u64 a, u64 b) {
    u64 d; asm("add.rn.f32x2 %0, %1, %2;" : "=l"(d) : "l"(a), "l"(b)); return d;
}
__device__ __forceinline__ u64 mul2(u64 a, u64 b) {
    u64 d; asm("mul.rn.f32x2 %0, %1, %2;" : "=l"(d) : "l"(a), "l"(b)); return d;
}
__device__ __forceinline__ float fast_sqrt(float x) {
    float r; asm("sqrt.approx.f32 %0, %1;" : "=f"(r) : "f"(x)); return r;
}
__device__ __forceinline__ float fast_rcp(float x) {
    float r; asm("rcp.approx.f32 %0, %1;" : "=f"(r) : "f"(x)); return r;
}

// per-layer scalar tail: (e0+e1) -> r -> h -> f1,f2; updates P1,P2; returns f1 pair
__device__ __forceinline__ u64 tail_step(u64 e0, u64 e1, ulonglong2 pab, u64 abp,
                                         u64& P1p, u64& P2p) {
    const u64 ONE2 = pk2(1.0f, 1.0f);
    u64 r2p = add2(e0, e1);
    float rA, rB; up2(rA, rB, r2p);
    u64 rp = pk2(fast_sqrt(rA), fast_sqrt(rB));
    u64 up = add2(pab.x, rp);                 // alpha + r
    float uA, uB; up2(uA, uB, up);
    u64 hp = pk2(fast_rcp(uA), fast_rcp(uB));
    u64 f1p = ffma2(pab.y, hp, ONE2);         // 1 + beta*h
    u64 f2p = ffma2(abp, mul2(hp, hp), ONE2); // 1 + alpha*beta*h^2
    P1p = mul2(P1p, f1p);
    P2p = mul2(P2p, f2p);
    return f1p;
}

// ---------------- setup kernel (1 block) ----------------
__global__ void setup_kernel(const float* __restrict__ la, const float* __restrict__ be,
                             const float* __restrict__ z0, const float* __restrict__ mean,
                             const float* __restrict__ cov) {
    __shared__ int s_bad;
    int t = threadIdx.x;
    if (t == 0) s_bad = 0;
    __syncthreads();

    // packed params per (layer, c-pair)
    for (int i = t; i < LL * 8; i += 256) {
        int l = i / 8, cp = i % 8;
        int c0 = 2 * cp, c1 = c0 + 1;
        float a0 = expf(la[l * CC + c0]), a1 = expf(la[l * CC + c1]);
        float b0 = be[l * CC + c0],       b1 = be[l * CC + c1];
        ulonglong2 v; v.x = pk2(a0, a1); v.y = pk2(b0, b1);
        g_parab[i] = v;
        g_parc[i]  = pk2(a0 * b0, a1 * b1);
    }
    // layer deltas, cp-innermost: index l*64 + j*8 + cp
    for (int i = t; i < LL * 8 * 8; i += 256) {
        int l = i / 64, rem = i % 64, j = rem / 8, cp = rem % 8;
        int c0 = 2 * cp, c1 = c0 + 1;
        int b0 = (l * CC + c0) * DIMN + 2 * j;
        int b1 = (l * CC + c1) * DIMN + 2 * j;
        float x0 = -z0[b0], y0 = -z0[b0 + 1];
        float x1 = -z0[b1], y1 = -z0[b1 + 1];
        if (l > 0) {
            int p0 = ((l - 1) * CC + c0) * DIMN + 2 * j;
            int p1 = ((l - 1) * CC + c1) * DIMN + 2 * j;
            x0 += z0[p0]; y0 += z0[p0 + 1];
            x1 += z0[p1]; y1 += z0[p1 + 1];
        }
        ulonglong2 v; v.x = pk2(x0, x1); v.y = pk2(y0, y1);
        g_negD2[i] = v;
    }
    // final offset: z0_5 - mean, cp-innermost: index j*8 + cp
    for (int i = t; i < 8 * 8; i += 256) {
        int j = i / 8, cp = i % 8;
        int c0 = 2 * cp, c1 = c0 + 1;
        int b0 = (5 * CC + c0) * DIMN + 2 * j;
        int b1 = (5 * CC + c1) * DIMN + 2 * j;
        int m0 = c0 * DIMN + 2 * j, m1 = c1 * DIMN + 2 * j;
        ulonglong2 v;
        v.x = pk2(z0[b0]     - mean[m0],     z0[b1]     - mean[m1]);
        v.y = pk2(z0[b0 + 1] - mean[m0 + 1], z0[b1 + 1] - mean[m1 + 1]);
        g_m52[i] = v;
    }

    // cov identity check, vectorized (1024 float4, 4 per thread)
    int bad = 0;
    const float4* cv4 = (const float4*)cov;
    for (int i = t; i < CC * DIMN * DIMN / 4; i += 256) {
        float4 v = cv4[i];
        int base = i * 4;
        int r0 = base % (DIMN * DIMN);
        float e0 = ((r0 % (DIMN + 1)) == 0) ? 1.0f : 0.0f;
        float e1 = (((r0 + 1) % (DIMN + 1)) == 0) ? 1.0f : 0.0f;
        float e2 = (((r0 + 2) % (DIMN + 1)) == 0) ? 1.0f : 0.0f;
        float e3 = (((r0 + 3) % (DIMN + 1)) == 0) ? 1.0f : 0.0f;
        if (v.x != e0 || v.y != e1 || v.z != e2 || v.w != e3) bad = 1;
    }
    if (bad) atomicOr(&s_bad, 1);
    __syncthreads();
    int id = (s_bad == 0) ? 1 : 0;
    if (t == 0) g_ident = id;

    int c = t;
    if (c < CC) {
        if (id) {
            g_hld[c] = 0.0f;
        } else {
            // general Cholesky + triangular inverse (cold path)
            float Lm[DIMN][DIMN];
            const float* A = cov + c * DIMN * DIMN;
            #pragma unroll 1
            for (int j = 0; j < DIMN; j++) {
                float s = A[j * DIMN + j];
                #pragma unroll 1
                for (int k = 0; k < j; k++) s -= Lm[j][k] * Lm[j][k];
                float d = sqrtf(s);
                Lm[j][j] = d;
                float inv = 1.0f / d;
                #pragma unroll 1
                for (int i = j + 1; i < DIMN; i++) {
                    float s2 = A[i * DIMN + j];
                    #pragma unroll 1
                    for (int k = 0; k < j; k++) s2 -= Lm[i][k] * Lm[j][k];
                    Lm[i][j] = s2 * inv;
                }
            }
            float hld = 0.0f;
            #pragma unroll 1
            for (int j = 0; j < DIMN; j++) hld += logf(Lm[j][j]);
            g_hld[c] = hld;

            float Li[DIMN][DIMN];
            #pragma unroll 1
            for (int j = 0; j < DIMN; j++) {
                for (int i = 0; i < DIMN; i++) Li[i][j] = 0.0f;
                Li[j][j] = 1.0f / Lm[j][j];
                #pragma unroll 1
                for (int i = j + 1; i < DIMN; i++) {
                    float s3 = 0.0f;
                    #pragma unroll 1
                    for (int k = j; k < i; k++) s3 += Lm[i][k] * Li[k][j];
                    Li[i][j] = -s3 / Lm[i][i];
                }
            }
            for (int i = 0; i < DIMN; i++)
                for (int j = 0; j < DIMN; j++)
                    g_Linv[(c * DIMN + i) * DIMN + j] = Li[i][j];
        }
    }
    __syncthreads();
    if (t < 8) g_hld2[t] = pk2(g_hld[2 * t], g_hld[2 * t + 1]);
}

// ---------------- main density kernel: 1 thread per point, software-pipelined ----------------
__global__ void __launch_bounds__(128, 5)
density_kernel(const float* __restrict__ z, float* __restrict__ out, int N)
{
    __shared__ ulonglong2 s_negD[LL * 8 * 8];     // 6 KB, index l*64 + j*8 + cp
    __shared__ ulonglong2 s_m5[8 * 8];            // 1 KB, index j*8 + cp
    __shared__ ulonglong2 s_parab[LL * 8];        // 768 B
    __shared__ u64        s_parc[LL * 8];         // 384 B
    __shared__ u64        s_hld2[8];

    int t = threadIdx.x;
    for (int i = t; i < LL * 8 * 8; i += 128) s_negD[i] = g_negD2[i];
    if (t < 8 * 8) s_m5[t] = g_m52[t];
    if (t < LL * 8) { s_parab[t] = g_parab[t]; s_parc[t] = g_parc[t]; }
    if (t < 8) s_hld2[t] = g_hld2[t];
    int ident = g_ident;
    __syncthreads();

    int n = blockIdx.x * 128 + t;
    if (n >= N) return;

    // z row as 16 scalar registers (pk2 broadcast on use in layer 0)
    const float4* zr = (const float4*)(z + (size_t)n * DIMN);
    float4 q0 = zr[0], q1 = zr[1], q2 = zr[2], q3 = zr[3];
    float zf[16] = { q0.x, q0.y, q0.z, q0.w, q1.x, q1.y, q1.z, q1.w,
                     q2.x, q2.y, q2.z, q2.w, q3.x, q3.y, q3.z, q3.w };

    const float HALF_DIM_LOG2PI = 14.7030165f;   // 0.5 * 16 * log(2*pi)
    const u64 ONE2 = pk2(1.0f, 1.0f);

    #pragma unroll 2
    for (int cp = 0; cp < 8; cp++) {
        const ulonglong2* dp = &s_negD[cp];

        u64 s[16];
        u64 e0 = 0ull, e1 = 0ull;

        // ---- layer 0: s = z - z0_0 ----
        #pragma unroll
        for (int j = 0; j < 8; j++) {
            ulonglong2 dd = dp[j * 8];
            u64 za = pk2(zf[2 * j],     zf[2 * j]);
            u64 zb = pk2(zf[2 * j + 1], zf[2 * j + 1]);
            s[2 * j]     = add2(za, dd.x);
            s[2 * j + 1] = add2(zb, dd.y);
            e0 = ffma2(s[2 * j],     s[2 * j],     e0);
            e1 = ffma2(s[2 * j + 1], s[2 * j + 1], e1);
        }

        u64 P1p = ONE2, P2p = ONE2, f1p;

        // ---- layers 1..5: prefetch layer-l deltas, then tail(l-1) over them, then update ----
        #pragma unroll
        for (int l = 1; l < LL; l++) {
            const ulonglong2* dl = dp + l * 64;
            // prefetch first half of layer l's deltas + params; MUFU tail below covers latency
            ulonglong2 p0 = dl[0], p1 = dl[8], p2 = dl[16], p3 = dl[24];
            ulonglong2 pab = s_parab[(l - 1) * 8 + cp];
            u64 abp = s_parc[(l - 1) * 8 + cp];

            f1p = tail_step(e0, e1, pab, abp, P1p, P2p);

            e0 = 0ull; e1 = 0ull;
            s[0] = ffma2(f1p, s[0], p0.x); s[1] = ffma2(f1p, s[1], p0.y);
            e0 = ffma2(s[0], s[0], e0);    e1 = ffma2(s[1], s[1], e1);
            s[2] = ffma2(f1p, s[2], p1.x); s[3] = ffma2(f1p, s[3], p1.y);
            e0 = ffma2(s[2], s[2], e0);    e1 = ffma2(s[3], s[3], e1);
            s[4] = ffma2(f1p, s[4], p2.x); s[5] = ffma2(f1p, s[5], p2.y);
            e0 = ffma2(s[4], s[4], e0);    e1 = ffma2(s[5], s[5], e1);
            s[6] = ffma2(f1p, s[6], p3.x); s[7] = ffma2(f1p, s[7], p3.y);
            e0 = ffma2(s[6], s[6], e0);    e1 = ffma2(s[7], s[7], e1);
            #pragma unroll
            for (int j = 4; j < 8; j++) {
                ulonglong2 dd = dl[j * 8];
                s[2 * j]     = ffma2(f1p, s[2 * j],     dd.x);
                s[2 * j + 1] = ffma2(f1p, s[2 * j + 1], dd.y);
                e0 = ffma2(s[2 * j],     s[2 * j],     e0);
                e1 = ffma2(s[2 * j + 1], s[2 * j + 1], e1);
            }
        }

        // ---- final: prefetch m5, tail(5), then q = |f1*s + m5|^2 ----
        const ulonglong2* mp = &s_m5[cp];
        ulonglong2 m0 = mp[0], m1 = mp[8], m2 = mp[16], m3 = mp[24];
        ulonglong2 pab5 = s_parab[5 * 8 + cp];
        u64 abp5 = s_parc[5 * 8 + cp];

        f1p = tail_step(e0, e1, pab5, abp5, P1p, P2p);

        float qA, qB;
        if (ident) {
            u64 a0 = 0ull, a1 = 0ull;
            u64 dx, dy;
            dx = ffma2(f1p, s[0], m0.x); dy = ffma2(f1p, s[1], m0.y);
            a0 = ffma2(dx, dx, a0);      a1 = ffma2(dy, dy, a1);
            dx = ffma2(f1p, s[2], m1.x); dy = ffma2(f1p, s[3], m1.y);
            a0 = ffma2(dx, dx, a0);      a1 = ffma2(dy, dy, a1);
            dx = ffma2(f1p, s[4], m2.x); dy = ffma2(f1p, s[5], m2.y);
            a0 = ffma2(dx, dx, a0);      a1 = ffma2(dy, dy, a1);
            dx = ffma2(f1p, s[6], m3.x); dy = ffma2(f1p, s[7], m3.y);
            a0 = ffma2(dx, dx, a0);      a1 = ffma2(dy, dy, a1);
            #pragma unroll
            for (int j = 4; j < 8; j++) {
                ulonglong2 mm = mp[j * 8];
                dx = ffma2(f1p, s[2 * j],     mm.x);
                dy = ffma2(f1p, s[2 * j + 1], mm.y);
                a0 = ffma2(dx, dx, a0);
                a1 = ffma2(dy, dy, a1);
            }
            u64 qp = add2(a0, a1);
            up2(qA, qB, qp);
        } else {
            // cold path: triangular solve with Linv from GLOBAL (perf irrelevant)
            float drA[DIMN], drB[DIMN];
            #pragma unroll
            for (int j = 0; j < 8; j++) {
                ulonglong2 mm = mp[j * 8];
                u64 dx = ffma2(f1p, s[2 * j],     mm.x);
                u64 dy = ffma2(f1p, s[2 * j + 1], mm.y);
                up2(drA[2 * j],     drB[2 * j],     dx);
                up2(drA[2 * j + 1], drB[2 * j + 1], dy);
            }
            qA = 0.0f; qB = 0.0f;
            const float* LpA = &g_Linv[2 * cp * DIMN * DIMN];
            const float* LpB = LpA + DIMN * DIMN;
            #pragma unroll 1
            for (int j = 0; j < DIMN; j++) {
                float sa = 0.0f, sb = 0.0f;
                #pragma unroll 1
                for (int i = 0; i <= j; i++) {
                    sa = fmaf(LpA[j * DIMN + i], drA[i], sa);
                    sb = fmaf(LpB[j * DIMN + i], drB[i], sb);
                }
                qA = fmaf(sa, sa, qA);
                qB = fmaf(sb, sb, qB);
            }
        }

        // log_det_jac total = log(P1^15 * P2), packed pow15
        u64 p2  = mul2(P1p, P1p);
        u64 p4  = mul2(p2, p2);
        u64 p8  = mul2(p4, p4);
        u64 g   = mul2(mul2(mul2(p8, p4), mul2(p2, P1p)), P2p);
        float gA, gB; up2(gA, gB, g);
        float hldA, hldB; up2(hldA, hldB, s_hld2[cp]);
        float vA = fmaf(-0.5f, qA, -HALF_DIM_LOG2PI) - hldA + __logf(gA);
        float vB = fmaf(-0.5f, qB, -HALF_DIM_LOG2PI) - hldB + __logf(gB);
        if (vA != vA) vA = __int_as_float(0xff800000);  // NaN -> -inf
        if (vB != vB) vB = __int_as_float(0xff800000);

        *(float2*)(out + (size_t)n * CC + 2 * cp) = make_float2(vA, vB);
    }
}

// ---------------- launch ----------------
extern "C" void kernel_launch(void* const* d_in, const int* in_sizes, int n_in,
                              void* d_out, int out_size) {
    const float* z    = (const float*)d_in[0];
    const float* z0   = (const float*)d_in[1];
    const float* la   = (const float*)d_in[2];
    const float* be   = (const float*)d_in[3];
    const float* mean = (const float*)d_in[4];
    const float* cov  = (const float*)d_in[5];
    float* out = (float*)d_out;

    int N = in_sizes[0] / DIMN;

    setup_kernel<<<1, 256>>>(la, be, z0, mean, cov);
    int blocks = (N + 127) / 128;
    density_kernel<<<blocks, 128>>>(z, out, N);
}